// round 7
// baseline (speedup 1.0000x reference)
#include <cuda_runtime.h>

// 2-layer LSTM (H=8, IN=2) + FC(8->1), T=1024, B=16384.
// 8 lanes per batch element, TWO elements per thread (low regs -> 12 warps/SM),
// fma.rn.f32x2 k-packed matvecs, smem h-broadcast, single-MUFU activations
// via tanh.approx.f32 with half-prescaled sigmoid-gate weights.

using u64 = unsigned long long;

__device__ __forceinline__ u64 pack2(float lo, float hi) {
    u64 r; asm("mov.b64 %0, {%1, %2};" : "=l"(r) : "f"(lo), "f"(hi)); return r;
}
__device__ __forceinline__ float2 unpack2(u64 v) {
    float2 f; asm("mov.b64 {%0, %1}, %2;" : "=f"(f.x), "=f"(f.y) : "l"(v)); return f;
}
__device__ __forceinline__ u64 ffma2(u64 a, u64 b, u64 c) {
    u64 d; asm("fma.rn.f32x2 %0, %1, %2, %3;" : "=l"(d) : "l"(a), "l"(b), "l"(c)); return d;
}
__device__ __forceinline__ float tanh_a(float x) {
    float y; asm("tanh.approx.f32 %0, %1;" : "=f"(y) : "f"(x)); return y;
}

__global__ void __launch_bounds__(32)
lstm2_fc_kernel(const float* __restrict__ x,
                const float* __restrict__ w_ih0, const float* __restrict__ w_hh0,
                const float* __restrict__ b_ih0, const float* __restrict__ b_hh0,
                const float* __restrict__ w_ih1, const float* __restrict__ w_hh1,
                const float* __restrict__ b_ih1, const float* __restrict__ b_hh1,
                const float* __restrict__ fc_w, const float* __restrict__ fc_b,
                float* __restrict__ out, int T, int B)
{
    // [elem p][pair-slot ql][hidden j]; store conflict-free, load broadcast.
    __shared__ alignas(16) float h0s[2][4][8];
    __shared__ alignas(16) float h1s[2][4][8];

    int lane  = threadIdx.x;
    int ql    = lane >> 3;         // pair slot within warp (0..3)
    int j     = lane & 7;          // hidden unit owned by this lane
    int tid   = blockIdx.x * 32 + lane;
    int q     = tid >> 3;          // global pair index: elements 2q, 2q+1
    int halfB = B >> 1;
    bool valid = (q < halfB);
    if (!valid) q = halfB - 1;

    // ---- Per-lane weights; sigmoid-gate rows (i,f,o) prescaled by 0.5 ----
    u64 wi0p[4], wh0p[4][4], wi1p[4][4], wh1p[4][4], zb0p[4], zb1p[4];
#pragma unroll
    for (int g = 0; g < 4; g++) {
        float sc = (g == 2) ? 1.0f : 0.5f;
        int r = g * 8 + j;
        wi0p[g] = pack2(sc * __ldg(&w_ih0[r * 2 + 0]), sc * __ldg(&w_ih0[r * 2 + 1]));
#pragma unroll
        for (int m = 0; m < 4; m++) {
            wh0p[g][m] = pack2(sc * __ldg(&w_hh0[r * 8 + 2 * m]), sc * __ldg(&w_hh0[r * 8 + 2 * m + 1]));
            wi1p[g][m] = pack2(sc * __ldg(&w_ih1[r * 8 + 2 * m]), sc * __ldg(&w_ih1[r * 8 + 2 * m + 1]));
            wh1p[g][m] = pack2(sc * __ldg(&w_hh1[r * 8 + 2 * m]), sc * __ldg(&w_hh1[r * 8 + 2 * m + 1]));
        }
        float zb0 = sc * (__ldg(&b_ih0[r]) + __ldg(&b_hh0[r]));
        float zb1 = sc * (__ldg(&b_ih1[r]) + __ldg(&b_hh1[r]));
        zb0p[g] = pack2(zb0, 0.0f);
        zb1p[g] = pack2(zb1, 0.0f);
    }

    // ---- State: 2 elements ----
    u64 h0p[2][4], h1p[2][4];
    float c0[2], c1[2];
    u64 zero2 = pack2(0.0f, 0.0f);
#pragma unroll
    for (int p = 0; p < 2; p++) {
        c0[p] = 0.0f; c1[p] = 0.0f;
#pragma unroll
        for (int m = 0; m < 4; m++) { h0p[p][m] = zero2; h1p[p][m] = zero2; }
    }

    // x: [T, B, 2] floats; elements 2q,2q+1 = one 16B load per step.
    int strideT = halfB;                        // ulonglong2 per timestep row
    const ulonglong2* xp = (const ulonglong2*)x + q;
    ulonglong2 xv = __ldg(xp);

#pragma unroll 1
    for (int t = 0; t < T; t++) {
        const ulonglong2* xn = xp + ((t + 1 < T) ? strideT : 0);
        ulonglong2 nx = __ldg(xn);

        u64 xq[2] = { xv.x, xv.y };

        // ---- Layer 0 ----
#pragma unroll
        for (int p = 0; p < 2; p++) {
            float z[4];
#pragma unroll
            for (int g = 0; g < 4; g++) {
                u64 acc = ffma2(wi0p[g], xq[p], zb0p[g]);
#pragma unroll
                for (int m = 0; m < 4; m++)
                    acc = ffma2(wh0p[g][m], h0p[p][m], acc);
                float2 u = unpack2(acc);
                z[g] = u.x + u.y;
            }
            float ig = fmaf(tanh_a(z[0]), 0.5f, 0.5f);
            float fg = fmaf(tanh_a(z[1]), 0.5f, 0.5f);
            float gg = tanh_a(z[2]);
            float og = fmaf(tanh_a(z[3]), 0.5f, 0.5f);
            c0[p] = fmaf(fg, c0[p], ig * gg);
            h0s[p][ql][j] = og * tanh_a(c0[p]);
        }
        __syncwarp();
#pragma unroll
        for (int p = 0; p < 2; p++) {
            const ulonglong2* row = (const ulonglong2*)&h0s[p][ql][0];
            ulonglong2 va = row[0], vb = row[1];
            h0p[p][0] = va.x; h0p[p][1] = va.y;
            h0p[p][2] = vb.x; h0p[p][3] = vb.y;
        }

        // ---- Layer 1 ----
#pragma unroll
        for (int p = 0; p < 2; p++) {
            float z[4];
#pragma unroll
            for (int g = 0; g < 4; g++) {
                u64 acc = ffma2(wi1p[g][0], h0p[p][0], zb1p[g]);
#pragma unroll
                for (int m = 1; m < 4; m++)
                    acc = ffma2(wi1p[g][m], h0p[p][m], acc);
#pragma unroll
                for (int m = 0; m < 4; m++)
                    acc = ffma2(wh1p[g][m], h1p[p][m], acc);
                float2 u = unpack2(acc);
                z[g] = u.x + u.y;
            }
            float ig = fmaf(tanh_a(z[0]), 0.5f, 0.5f);
            float fg = fmaf(tanh_a(z[1]), 0.5f, 0.5f);
            float gg = tanh_a(z[2]);
            float og = fmaf(tanh_a(z[3]), 0.5f, 0.5f);
            c1[p] = fmaf(fg, c1[p], ig * gg);
            h1s[p][ql][j] = og * tanh_a(c1[p]);
        }
        __syncwarp();
#pragma unroll
        for (int p = 0; p < 2; p++) {
            const ulonglong2* row = (const ulonglong2*)&h1s[p][ql][0];
            ulonglong2 va = row[0], vb = row[1];
            h1p[p][0] = va.x; h1p[p][1] = va.y;
            h1p[p][2] = vb.x; h1p[p][3] = vb.y;
        }

        xv = nx; xp = xn;
    }

    // ---- FC: out[b] = fc_w . h1_last + fc_b (lane j==0 writes 2) ----
    if (valid && j == 0) {
        float fw[8];
#pragma unroll
        for (int k = 0; k < 8; k++) fw[k] = __ldg(&fc_w[k]);
        float fb = __ldg(&fc_b[0]);
        float2 o;
        float* op = &o.x;
#pragma unroll
        for (int p = 0; p < 2; p++) {
            float acc = fb;
#pragma unroll
            for (int m = 0; m < 4; m++) {
                float2 u = unpack2(h1p[p][m]);
                acc = fmaf(fw[2 * m], u.x, acc);
                acc = fmaf(fw[2 * m + 1], u.y, acc);
            }
            op[p] = acc;
        }
        *(float2*)&out[2 * q] = o;
    }
}

extern "C" void kernel_launch(void* const* d_in, const int* in_sizes, int n_in,
                              void* d_out, int out_size)
{
    const float* x      = (const float*)d_in[0];
    const float* w_ih0  = (const float*)d_in[1];
    const float* w_hh0  = (const float*)d_in[2];
    const float* b_ih0  = (const float*)d_in[3];
    const float* b_hh0  = (const float*)d_in[4];
    const float* w_ih1  = (const float*)d_in[5];
    const float* w_hh1  = (const float*)d_in[6];
    const float* b_ih1  = (const float*)d_in[7];
    const float* b_hh1  = (const float*)d_in[8];
    const float* fc_w   = (const float*)d_in[9];
    const float* fc_b   = (const float*)d_in[10];
    float* out = (float*)d_out;

    int B = out_size;                 // [B, 1]
    int T = in_sizes[0] / (2 * B);    // x: [T, B, 2]

    int threads = 32;
    int total   = (B / 2) * 8;        // 8 lanes per element pair
    int blocks  = (total + threads - 1) / threads;
    lstm2_fc_kernel<<<blocks, threads>>>(x, w_ih0, w_hh0, b_ih0, b_hh0,
                                         w_ih1, w_hh1, b_ih1, b_hh1,
                                         fc_w, fc_b, out, T, B);
}